// round 14
// baseline (speedup 1.0000x reference)
#include <cuda_runtime.h>
#include <cuda_fp16.h>
#include <cstdint>

// Problem constants
#define NIMG   128          // images per input
#define NTOT   256          // stacked rows (a then b)
#define CCH    16           // channels
#define HP     16           // pooled H
#define WP     16           // pooled W
#define DDIM   4096         // CCH*HP*WP
#define TILE   32           // pair tile edge
#define NTROW  8            // NTOT/TILE
#define NTILES 36           // upper-tri tiles: 8*9/2
#define DCHUNK 256          // d per block (pair kernel)
#define NDCH   16           // DDIM/DCHUNK
#define DSTEP  32           // smem staging depth
#define NSTEPS (DCHUNK / DSTEP)      // 8
#define NBLK_MAIN  (NTILES * NDCH)   // 576 main blocks
#define NBLK_COUNT (NBLK_MAIN + 1)   // + 1 bias-sampling block

// sqrt(0.5*log2(e)) folded into the pooled means: term = ex2(-(d'*r)^2) * r.
#define SQRT_K      0.8493218003f
#define MEAN_SCALE  (0.25f * SQRT_K)

// Scratch.
// f32 pooled data [d][n] — bias-sampler reference AND identical-value source
// for the packed array below.
__device__ float g_Mt[DDIM * NTOT];
__device__ float g_Vt[DDIM * NTOT];
// Interleaved packed pooled data: g_MV[d*128 + q] = {m[2q], m[2q+1], v[2q], v[2q+1]}
__device__ float4 g_MV[DDIM * (NTOT / 2)];
__device__ double g_acc;          // zero-init; reset by last block each run
__device__ unsigned int g_done;   // zero-init; reset by last block each run

__device__ __forceinline__ float rsqrt_approx(float x) {
    float y; asm("rsqrt.approx.ftz.f32 %0, %1;" : "=f"(y) : "f"(x)); return y;
}
__device__ __forceinline__ float ex2f32(float x) {
    float y; asm("ex2.approx.ftz.f32 %0, %1;" : "=f"(y) : "f"(x)); return y;
}
__device__ __forceinline__ __half2 h2ex2(__half2 x) {
    unsigned xi = *reinterpret_cast<unsigned*>(&x), yi;
    asm("ex2.approx.f16x2 %0, %1;" : "=r"(yi) : "r"(xi));
    return *reinterpret_cast<__half2*>(&yi);
}

// ---------------------------------------------------------------------------
// Pooling: one block per (ph, c, half). 256 threads. Processes BOTH mu and
// logvar for its half; writes the f32 [d][n] arrays and the packed float4.
// ---------------------------------------------------------------------------
__global__ __launch_bounds__(256) void pool_kernel(
    const float* __restrict__ mu_a, const float* __restrict__ lv_a,
    const float* __restrict__ mu_b, const float* __restrict__ lv_b)
{
    const int ph  = blockIdx.x;      // 0..15
    const int c   = blockIdx.y;      // 0..15
    const int hf  = blockIdx.z;      // 0: a-rows, 1: b-rows
    const int tid = threadIdx.x;

    const float* muSrc = hf ? mu_b : mu_a;
    const float* lvSrc = hf ? lv_b : lv_a;
    const int n_off = hf * NIMG;

    __shared__ float sM[NIMG * 17];
    __shared__ float sV[NIMG * 17];

    const float2* mu2 = reinterpret_cast<const float2*>(muSrc);
    const float2* lv2 = reinterpret_cast<const float2*>(lvSrc);

    #pragma unroll
    for (int k = 0; k < 8; k++) {
        int o  = tid + 256 * k;      // 0..2047
        int n  = o >> 4;
        int pw = o & 15;
        int i2 = n * 8192 + c * 512 + ph * 32 + pw;
        float2 a0 = mu2[i2];
        float2 a1 = mu2[i2 + 16];
        sM[n * 17 + pw] = (a0.x + a0.y + a1.x + a1.y) * MEAN_SCALE;
        float2 b0 = lv2[i2];
        float2 b1 = lv2[i2 + 16];
        sV[n * 17 + pw] = (__expf(b0.x) + __expf(b0.y) + __expf(b1.x) + __expf(b1.y)) * 0.0625f;
    }
    __syncthreads();

    // f32 writes (sampler reference)
    const int dbase = ((c * 16 + ph) * 16) * NTOT + n_off;
    #pragma unroll
    for (int k = 0; k < 8; k++) {
        int o  = tid + 256 * k;
        int pw = o >> 7;
        int n  = o & 127;
        g_Mt[dbase + pw * NTOT + n] = sM[n * 17 + pw];
        g_Vt[dbase + pw * NTOT + n] = sV[n * 17 + pw];
    }

    // packed float4 writes: 16 pw x 64 q
    const int pbase = ((c * 16 + ph) * 16) * (NTOT / 2) + n_off / 2;
    #pragma unroll
    for (int k = 0; k < 4; k++) {
        int o  = tid + 256 * k;      // 0..1023
        int pw = o >> 6;
        int q  = o & 63;
        float4 val;
        val.x = sM[(2 * q) * 17 + pw];
        val.y = sM[(2 * q + 1) * 17 + pw];
        val.z = sV[(2 * q) * 17 + pw];
        val.w = sV[(2 * q + 1) * 17 + pw];
        g_MV[pbase + pw * (NTOT / 2) + q] = val;
    }
}

// ---------------------------------------------------------------------------
// Pair kernel: 576 main blocks (36 upper-tri tiles x 16 d-chunks) + 1 bias
// sampling block. Double-buffered smem of packed float4 {m0,m1,v0,v1};
// one LDS.128 per side per bundle. fp16x2 ex2 shared across 2 terms, HFMA2
// accumulate flushed to f32 every 32 dims.
// __launch_bounds__(256, 5): cap regs at 51 to get 5 blocks/SM (was 4) and
// better MUFU latency hiding.
//
// Systematic fp16 bias cancels to -256*bbar_offdiag (since sum s_i s_j = 0);
// the sampler block estimates bbar against the f32 reference and corrects.
// ---------------------------------------------------------------------------
__global__ __launch_bounds__(256, 5) void pair_kernel(float* __restrict__ out)
{
    const int tid = threadIdx.x;
    __shared__ float warpsum[8];

    double myContribution = 0.0;

    if (blockIdx.x < NBLK_MAIN) {
        // ---- main pair block ----
        const int tileIdx = blockIdx.x % NTILES;
        const int dch     = blockIdx.x / NTILES;

        int rem = tileIdx;
        int ti = 0;
        while (rem >= NTROW - ti) { rem -= NTROW - ti; ti++; }
        const int tj = ti + rem;

        const int i0h = ti * (TILE / 2);   // float4-index offset of i-tile
        const int j0h = tj * (TILE / 2);
        const int d0  = dch * DCHUNK;

        const int jx = tid & 15;          // j pair index within tile
        const int iy = tid >> 4;          // i pair index within tile

        __shared__ __align__(16) float4 sI[2][DSTEP * 16];
        __shared__ __align__(16) float4 sJ[2][DSTEP * 16];

        float facc0 = 0.f, facc1 = 0.f;

        // loaders: thread covers (dd0, q0) and (dd0+16, q0) for both I and J
        const int dd0 = tid >> 4;     // 0..15
        const int q0  = tid & 15;

        float4 pI0, pI1, pJ0, pJ1;
        {
            int gA = (d0 + dd0) * (NTOT / 2);
            int gB = (d0 + dd0 + 16) * (NTOT / 2);
            pI0 = g_MV[gA + i0h + q0];
            pI1 = g_MV[gB + i0h + q0];
            pJ0 = g_MV[gA + j0h + q0];
            pJ1 = g_MV[gB + j0h + q0];
        }
        sI[0][dd0 * 16 + q0]        = pI0;
        sI[0][(dd0 + 16) * 16 + q0] = pI1;
        sJ[0][dd0 * 16 + q0]        = pJ0;
        sJ[0][(dd0 + 16) * 16 + q0] = pJ1;

        #pragma unroll
        for (int s = 0; s < NSTEPS; s++) {
            const int p = s & 1;
            __syncthreads();

            if (s + 1 < NSTEPS) {
                int gA = (d0 + (s + 1) * DSTEP + dd0) * (NTOT / 2);
                int gB = (d0 + (s + 1) * DSTEP + dd0 + 16) * (NTOT / 2);
                pI0 = g_MV[gA + i0h + q0];
                pI1 = g_MV[gB + i0h + q0];
                pJ0 = g_MV[gA + j0h + q0];
                pJ1 = g_MV[gB + j0h + q0];
            }

            __half2 hacc0 = __floats2half2_rn(0.f, 0.f);
            __half2 hacc1 = __floats2half2_rn(0.f, 0.f);

            #pragma unroll 8
            for (int dd = 0; dd < DSTEP; dd++) {
                float4 I = sI[p][dd * 16 + iy];   // {mi0, mi1, vi0, vi1}
                float4 J = sJ[p][dd * 16 + jx];   // {mj0, mj1, vj0, vj1}

                // row 0 (I.x, I.z) vs j-pair
                {
                    float s0 = I.z + J.z, s1 = I.z + J.w;
                    float r0 = rsqrt_approx(s0), r1 = rsqrt_approx(s1);
                    float t0 = (I.x - J.x) * r0;
                    float t1 = (I.x - J.y) * r1;
                    __half2 e = h2ex2(__floats2half2_rn(-t0 * t0, -t1 * t1));
                    hacc0 = __hfma2(e, __floats2half2_rn(r0, r1), hacc0);
                }
                // row 1 (I.y, I.w) vs j-pair
                {
                    float s0 = I.w + J.z, s1 = I.w + J.w;
                    float r0 = rsqrt_approx(s0), r1 = rsqrt_approx(s1);
                    float t0 = (I.y - J.x) * r0;
                    float t1 = (I.y - J.y) * r1;
                    __half2 e = h2ex2(__floats2half2_rn(-t0 * t0, -t1 * t1));
                    hacc1 = __hfma2(e, __floats2half2_rn(r0, r1), hacc1);
                }
            }

            facc0 += __low2float(hacc0) + __high2float(hacc0);
            facc1 += __low2float(hacc1) + __high2float(hacc1);

            if (s + 1 < NSTEPS) {
                int q = 1 - p;
                sI[q][dd0 * 16 + q0]        = pI0;
                sI[q][(dd0 + 16) * 16 + q0] = pI1;
                sJ[q][dd0 * 16 + q0]        = pJ0;
                sJ[q][(dd0 + 16) * 16 + q0] = pJ1;
            }
        }

        float v = facc0 + facc1;
        #pragma unroll
        for (int o = 16; o; o >>= 1) v += __shfl_xor_sync(0xffffffffu, v, o);
        if ((tid & 31) == 0) warpsum[tid >> 5] = v;
        __syncthreads();
        if (tid == 0) {
            float b = 0.f;
            #pragma unroll
            for (int k = 0; k < 8; k++) b += warpsum[k];
            double sgn = ((ti < 4) == (tj < 4)) ? 1.0 : -1.0;
            double w   = (ti == tj) ? sgn : 2.0 * sgn;
            myContribution = (double)b * w;
        }
    } else {
        // ---- bias sampling block (R9-validated: 128 term-samples/thread,
        //      coefficient 32 = 256 * 4096 / 32768) ----
        const int p0 = tid;
        const int p1 = (tid + 1) & 255;
        float S16 = 0.f, S32 = 0.f;

        #pragma unroll 1
        for (int db = 0; db < 128; db += 32) {
            __half2 hacc = __floats2half2_rn(0.f, 0.f);
            float s32 = 0.f;
            #pragma unroll
            for (int dd = 0; dd < 32; dd += 2) {
                int d = db + dd;
                float m00 = g_Mt[d * NTOT + p0],       m01 = g_Mt[d * NTOT + p1];
                float v00 = g_Vt[d * NTOT + p0],       v01 = g_Vt[d * NTOT + p1];
                float m10 = g_Mt[(d + 1) * NTOT + p0], m11 = g_Mt[(d + 1) * NTOT + p1];
                float v10 = g_Vt[(d + 1) * NTOT + p0], v11 = g_Vt[(d + 1) * NTOT + p1];

                float s0 = v00 + v01, s1 = v10 + v11;
                float r0 = rsqrt_approx(s0), r1 = rsqrt_approx(s1);
                float t0 = (m00 - m01) * r0;
                float t1 = (m10 - m11) * r1;
                float u0 = -t0 * t0, u1 = -t1 * t1;
                // f32 reference path
                s32 = fmaf(ex2f32(u0), r0, s32);
                s32 = fmaf(ex2f32(u1), r1, s32);
                // f16 path (identical op sequence to the main loop)
                __half2 e = h2ex2(__floats2half2_rn(u0, u1));
                hacc = __hfma2(e, __floats2half2_rn(r0, r1), hacc);
            }
            S16 += __low2float(hacc) + __high2float(hacc);
            S32 += s32;
        }

        float diff = S16 - S32;
        #pragma unroll
        for (int o = 16; o; o >>= 1) diff += __shfl_xor_sync(0xffffffffu, diff, o);
        if ((tid & 31) == 0) warpsum[tid >> 5] = diff;
        __syncthreads();
        if (tid == 0) {
            float dsum = 0.f;
            #pragma unroll
            for (int k = 0; k < 8; k++) dsum += warpsum[k];
            myContribution = 32.0 * (double)dsum;
        }
    }

    if (tid == 0) {
        atomicAdd(&g_acc, myContribution);
        __threadfence();
        unsigned n = atomicAdd(&g_done, 1u);
        if (n == NBLK_COUNT - 1) {
            __threadfence();
            double total = *((volatile double*)&g_acc);
            out[0] = (float)total;
            // reset for the next (graph-replayed) run
            *((volatile double*)&g_acc) = 0.0;
            *((volatile unsigned*)&g_done) = 0u;
            __threadfence();
        }
    }
}

extern "C" void kernel_launch(void* const* d_in, const int* in_sizes, int n_in,
                              void* d_out, int out_size)
{
    const float* mu_a = (const float*)d_in[0];
    const float* lv_a = (const float*)d_in[1];
    const float* mu_b = (const float*)d_in[2];
    const float* lv_b = (const float*)d_in[3];
    float* out = (float*)d_out;

    pool_kernel<<<dim3(HP, CCH, 2), 256>>>(mu_a, lv_a, mu_b, lv_b);
    pair_kernel<<<NBLK_COUNT, 256>>>(out);
}